// round 6
// baseline (speedup 1.0000x reference)
#include <cuda_runtime.h>
#include <math.h>

#define BATCH  4
#define LSEQ   8192
#define NHEADS 8
#define HEAD   64
#define NV     128
#define PP     64
#define DMODEL 512

#define XS 68      // stride for 64-wide tiles: bank = 4r+c -> conflict-free frags
#define PS 132     // stride for 128-wide P tile: bank = 4r+c

// smem (floats): Xs 128*68, Qs 128*68, Ks 128*68, W1s 64*68, W2s 64*68,
//                Ps 128*132, b1s 64, b2s 64, redm 256, reds 256
#define OFF_X   0
#define OFF_Q   (NV*XS)
#define OFF_K   (2*NV*XS)
#define OFF_W1  (3*NV*XS)
#define OFF_W2  (3*NV*XS + HEAD*XS)
#define OFF_P   (3*NV*XS + 2*HEAD*XS)
#define OFF_B1  (OFF_P + NV*PS)
#define OFF_B2  (OFF_B1 + HEAD)
#define OFF_RM  (OFF_B2 + HEAD)
#define OFF_RS  (OFF_RM + 256)
#define SMEM_FLOATS (OFF_RS + 256)
#define SMEM_BYTES  (SMEM_FLOATS * 4)

__device__ __forceinline__ float to_tf32(float x) {
    float y;
    asm("cvt.rna.tf32.f32 %0, %1;" : "=f"(y) : "f"(x));
    return y;
}

__device__ __forceinline__ void split_tf32(float v, float& hi, float& lo) {
    hi = to_tf32(v);
    lo = to_tf32(v - hi);
}

__device__ __forceinline__ void mma8(float c[4], const float a[4], const float b[2]) {
    asm volatile(
        "mma.sync.aligned.m16n8k8.row.col.f32.tf32.tf32.f32 "
        "{%0,%1,%2,%3}, {%4,%5,%6,%7}, {%8,%9}, {%0,%1,%2,%3};"
        : "+f"(c[0]), "+f"(c[1]), "+f"(c[2]), "+f"(c[3])
        : "r"(__float_as_uint(a[0])), "r"(__float_as_uint(a[1])),
          "r"(__float_as_uint(a[2])), "r"(__float_as_uint(a[3])),
          "r"(__float_as_uint(b[0])), "r"(__float_as_uint(b[1])));
}

__device__ __forceinline__ void pair_bar(int wp) {
    asm volatile("bar.sync %0, %1;" :: "r"(wp + 1), "r"(64) : "memory");
}

__global__ __launch_bounds__(512, 1)
void sg_tc3_kernel(const float* __restrict__ x,
                   const float* __restrict__ w1, const float* __restrict__ b1,
                   const float* __restrict__ w2, const float* __restrict__ b2,
                   float* __restrict__ out)
{
    extern __shared__ float sm[];
    float* Xs  = sm + OFF_X;
    float* Qs  = sm + OFF_Q;
    float* Ks  = sm + OFF_K;
    float* W1s = sm + OFF_W1;
    float* W2s = sm + OFF_W2;
    float* Ps  = sm + OFF_P;
    float* b1s = sm + OFF_B1;
    float* b2s = sm + OFF_B2;
    float* redm = sm + OFF_RM;   // [2][128] half-row maxes
    float* reds = sm + OFF_RS;   // [2][128] half-row sums

    const int tid = threadIdx.x;
    const int bid = blockIdx.x;
    const int b   = bid >> 9;
    const int rem = bid & 511;
    const int h   = rem >> 6;
    const int p   = rem & 63;

    // ---- Phase A: load X, W1, W2 (fp32 originals), biases ----
    for (int idx = tid; idx < HEAD * HEAD; idx += 512) {
        int r = idx >> 6, c = idx & 63;
        W1s[r * XS + c] = w1[idx];
        W2s[r * XS + c] = w2[idx];
    }
    if (tid < HEAD) { b1s[tid] = b1[tid]; b2s[tid] = b2[tid]; }

    const float* xbase = x + ((size_t)b * LSEQ + p) * DMODEL + h * HEAD;
    for (int idx = tid; idx < NV * HEAD; idx += 512) {
        int i = idx >> 6, d = idx & 63;
        Xs[i * XS + d] = xbase[(size_t)i * (PP * DMODEL) + d];
    }
    __syncthreads();

    const int warp = tid >> 5;
    const int lane = tid & 31;
    const int lr = lane >> 2;
    const int lc = lane & 3;
    const int wp = warp >> 1;    // row-pair 0..7 -> rows [16wp, 16wp+16)
    const int wh = warp & 1;     // column half
    const int m0 = wp * 16;

    // ---- Phase B: Q = X W1^T + b1, K = X W2^T + b2 (split-tf32, 3-term) ----
    {
        float cq[4][4], ck[4][4];
        #pragma unroll
        for (int n = 0; n < 4; n++)
            #pragma unroll
            for (int q = 0; q < 4; q++) { cq[n][q] = 0.f; ck[n][q] = 0.f; }

        const int d0b = 32 * wh;
        const int rA0 = (m0 + lr) * XS, rA1 = (m0 + lr + 8) * XS;
        #pragma unroll
        for (int k = 0; k < 8; k++) {
            const int e0 = k * 8;
            float ahi[4], alo[4];
            split_tf32(Xs[rA0 + e0 + lc],     ahi[0], alo[0]);
            split_tf32(Xs[rA1 + e0 + lc],     ahi[1], alo[1]);
            split_tf32(Xs[rA0 + e0 + lc + 4], ahi[2], alo[2]);
            split_tf32(Xs[rA1 + e0 + lc + 4], ahi[3], alo[3]);
            #pragma unroll
            for (int n = 0; n < 4; n++) {
                const int rB = (d0b + n * 8 + lr) * XS + e0 + lc;
                float bh[2], bl[2];
                split_tf32(W1s[rB],     bh[0], bl[0]);
                split_tf32(W1s[rB + 4], bh[1], bl[1]);
                mma8(cq[n], ahi, bh);
                mma8(cq[n], ahi, bl);
                mma8(cq[n], alo, bh);
                split_tf32(W2s[rB],     bh[0], bl[0]);
                split_tf32(W2s[rB + 4], bh[1], bl[1]);
                mma8(ck[n], ahi, bh);
                mma8(ck[n], ahi, bl);
                mma8(ck[n], alo, bh);
            }
        }
        #pragma unroll
        for (int n = 0; n < 4; n++) {
            const int d0 = d0b + n * 8 + 2 * lc;
            const float bq0 = b1s[d0], bq1 = b1s[d0 + 1];
            const float bk0 = b2s[d0], bk1 = b2s[d0 + 1];
            const int i0 = (m0 + lr) * XS + d0, i1 = (m0 + lr + 8) * XS + d0;
            *(float2*)(Qs + i0) = make_float2(cq[n][0] + bq0, cq[n][1] + bq1);
            *(float2*)(Qs + i1) = make_float2(cq[n][2] + bq0, cq[n][3] + bq1);
            *(float2*)(Ks + i0) = make_float2(ck[n][0] + bk0, ck[n][1] + bk1);
            *(float2*)(Ks + i1) = make_float2(ck[n][2] + bk0, ck[n][3] + bk1);
        }
    }
    __syncthreads();

    // ---- Phase C: S = Q K^T (split-tf32), gelu, register softmax ----
    float cs[8][4];
    #pragma unroll
    for (int n = 0; n < 8; n++)
        #pragma unroll
        for (int q = 0; q < 4; q++) cs[n][q] = 0.f;

    {
        const int c0 = 64 * wh;
        const int rA0 = (m0 + lr) * XS, rA1 = (m0 + lr + 8) * XS;
        #pragma unroll
        for (int k = 0; k < 8; k++) {
            const int e0 = k * 8;
            float ahi[4], alo[4];
            split_tf32(Qs[rA0 + e0 + lc],     ahi[0], alo[0]);
            split_tf32(Qs[rA1 + e0 + lc],     ahi[1], alo[1]);
            split_tf32(Qs[rA0 + e0 + lc + 4], ahi[2], alo[2]);
            split_tf32(Qs[rA1 + e0 + lc + 4], ahi[3], alo[3]);
            #pragma unroll
            for (int n = 0; n < 8; n++) {
                const int rB = (c0 + n * 8 + lr) * XS + e0 + lc;
                float bh[2], bl[2];
                split_tf32(Ks[rB],     bh[0], bl[0]);
                split_tf32(Ks[rB + 4], bh[1], bl[1]);
                mma8(cs[n], ahi, bh);
                mma8(cs[n], ahi, bl);
                mma8(cs[n], alo, bh);
            }
        }
    }

    // gelu (exact)
    #pragma unroll
    for (int n = 0; n < 8; n++)
        #pragma unroll
        for (int q = 0; q < 4; q++) {
            float s = cs[n][q];
            cs[n][q] = 0.5f * s * (1.0f + erff(s * 0.70710678118654752f));
        }

    // row maxes (rows m0+lr and m0+lr+8): in-thread then quad butterfly
    {
        float mA = -1e30f, mB = -1e30f;
        #pragma unroll
        for (int n = 0; n < 8; n++) {
            mA = fmaxf(mA, fmaxf(cs[n][0], cs[n][1]));
            mB = fmaxf(mB, fmaxf(cs[n][2], cs[n][3]));
        }
        mA = fmaxf(mA, __shfl_xor_sync(0xFFFFFFFF, mA, 1));
        mA = fmaxf(mA, __shfl_xor_sync(0xFFFFFFFF, mA, 2));
        mB = fmaxf(mB, __shfl_xor_sync(0xFFFFFFFF, mB, 1));
        mB = fmaxf(mB, __shfl_xor_sync(0xFFFFFFFF, mB, 2));
        if (lc == 0) {
            redm[wh * 128 + m0 + lr]     = mA;
            redm[wh * 128 + m0 + lr + 8] = mB;
        }
        pair_bar(wp);
        mA = fmaxf(redm[m0 + lr],     redm[128 + m0 + lr]);
        mB = fmaxf(redm[m0 + lr + 8], redm[128 + m0 + lr + 8]);

        // exp + row sums
        float sA = 0.f, sB = 0.f;
        #pragma unroll
        for (int n = 0; n < 8; n++) {
            cs[n][0] = __expf(cs[n][0] - mA); sA += cs[n][0];
            cs[n][1] = __expf(cs[n][1] - mA); sA += cs[n][1];
            cs[n][2] = __expf(cs[n][2] - mB); sB += cs[n][2];
            cs[n][3] = __expf(cs[n][3] - mB); sB += cs[n][3];
        }
        sA += __shfl_xor_sync(0xFFFFFFFF, sA, 1);
        sA += __shfl_xor_sync(0xFFFFFFFF, sA, 2);
        sB += __shfl_xor_sync(0xFFFFFFFF, sB, 1);
        sB += __shfl_xor_sync(0xFFFFFFFF, sB, 2);
        if (lc == 0) {
            reds[wh * 128 + m0 + lr]     = sA;
            reds[wh * 128 + m0 + lr + 8] = sB;
        }
        pair_bar(wp);
        const float invA = 1.0f / (reds[m0 + lr]     + reds[128 + m0 + lr]);
        const float invB = 1.0f / (reds[m0 + lr + 8] + reds[128 + m0 + lr + 8]);

        // write normalized P (tf32-rounded), own half-columns of own 16 rows
        #pragma unroll
        for (int n = 0; n < 8; n++) {
            const int col = 64 * wh + n * 8 + 2 * lc;
            *(float2*)(Ps + (m0 + lr) * PS + col) =
                make_float2(to_tf32(cs[n][0] * invA), to_tf32(cs[n][1] * invA));
            *(float2*)(Ps + (m0 + lr + 8) * PS + col) =
                make_float2(to_tf32(cs[n][2] * invB), to_tf32(cs[n][3] * invB));
        }
        pair_bar(wp);
    }

    // ---- Phase D: Y = P X (single-term tf32) ----
    {
        float cy[4][4];
        #pragma unroll
        for (int n = 0; n < 4; n++)
            #pragma unroll
            for (int q = 0; q < 4; q++) cy[n][q] = 0.f;

        const int d0b = 32 * wh;
        const int pA0 = (m0 + lr) * PS, pA1 = (m0 + lr + 8) * PS;
        #pragma unroll
        for (int k = 0; k < 16; k++) {
            const int j0 = k * 8;
            float a[4] = { Ps[pA0 + j0 + lc],     Ps[pA1 + j0 + lc],
                           Ps[pA0 + j0 + lc + 4], Ps[pA1 + j0 + lc + 4] };
            #pragma unroll
            for (int n = 0; n < 4; n++) {
                const int d0 = d0b + n * 8;
                float bf[2] = { to_tf32(Xs[(j0 + lc) * XS + d0 + lr]),
                                to_tf32(Xs[(j0 + lc + 4) * XS + d0 + lr]) };
                mma8(cy[n], a, bf);
            }
        }

        const size_t ob0 = ((size_t)b * LSEQ + (size_t)(m0 + lr) * PP + p) * DMODEL + h * HEAD;
        const size_t ob1 = ((size_t)b * LSEQ + (size_t)(m0 + lr + 8) * PP + p) * DMODEL + h * HEAD;
        #pragma unroll
        for (int n = 0; n < 4; n++) {
            const int d0 = d0b + n * 8 + 2 * lc;
            *(float2*)(out + ob0 + d0) = make_float2(cy[n][0], cy[n][1]);
            *(float2*)(out + ob1 + d0) = make_float2(cy[n][2], cy[n][3]);
        }
    }
}

extern "C" void kernel_launch(void* const* d_in, const int* in_sizes, int n_in,
                              void* d_out, int out_size)
{
    const float* x  = (const float*)d_in[0];
    const float* w1 = (const float*)d_in[1];
    const float* b1 = (const float*)d_in[2];
    const float* w2 = (const float*)d_in[3];
    const float* b2 = (const float*)d_in[4];
    float* out = (float*)d_out;

    cudaFuncSetAttribute(sg_tc3_kernel, cudaFuncAttributeMaxDynamicSharedMemorySize, SMEM_BYTES);
    sg_tc3_kernel<<<BATCH * NHEADS * PP, 512, SMEM_BYTES>>>(x, w1, b1, w2, b2, out);
}

// round 13
// speedup vs baseline: 1.6772x; 1.6772x over previous
#include <cuda_runtime.h>
#include <cuda_bf16.h>
#include <cstdint>
#include <math.h>

#define BATCH  4
#define LSEQ   8192
#define NHEADS 8
#define HEAD   64
#define NV     128
#define PP     64
#define DMODEL 512

// strides in 32-bit words; 36%32==4 and 68%32==4 -> bank = 4*row + col (conflict-free frags)
#define WS  36    // 64-col bf16 tiles (32 data words + 4 pad)
#define PWS 68    // 128-col bf16 tiles (64 data words + 4 pad)

// smem word offsets
#define O_B1   0
#define O_B2   64
#define O_RM   128                  // [2][128] row-max partials
#define O_RS   384                  // [2][128] row-sum partials
#define O_XHI  640
#define O_XLO  (O_XHI + 128*WS)     // 5248
#define O_W1HI (O_XLO + 128*WS)     // 9856
#define O_W1LO (O_W1HI + 64*WS)
#define O_W2HI (O_W1LO + 64*WS)
#define O_W2LO (O_W2HI + 64*WS)
#define O_XTHI (O_W2LO + 64*WS)     // 19072  X^T [64 x 128]
#define O_XTLO (O_XTHI + 64*PWS)
#define O_QHI  (O_XTLO + 64*PWS)    // 27776
#define O_QLO  (O_QHI + 128*WS)
#define O_KHI  (O_QLO + 128*WS)
#define O_KLO  (O_KHI + 128*WS)
#define SMEM_WORDS (O_KLO + 128*WS) // 46208
#define SMEM_BYTES (SMEM_WORDS * 4) // 184832

// P [128 x 128] hi/lo overlays X (dead after phase B) and W1/W2 (dead after phase B)
#define O_PHI  O_XHI                // needs 128*68=8704 <= 9216 (X region)
#define O_PLO  O_W1HI               // needs 8704 <= 9216 (W region)

__device__ __forceinline__ void mma16(float c[4], const uint32_t a[4], const uint32_t b[2]) {
    asm volatile(
        "mma.sync.aligned.m16n8k16.row.col.f32.bf16.bf16.f32 "
        "{%0,%1,%2,%3}, {%4,%5,%6,%7}, {%8,%9}, {%0,%1,%2,%3};"
        : "+f"(c[0]), "+f"(c[1]), "+f"(c[2]), "+f"(c[3])
        : "r"(a[0]), "r"(a[1]), "r"(a[2]), "r"(a[3]), "r"(b[0]), "r"(b[1]));
}

// split two floats into packed bf16x2 hi and lo words
__device__ __forceinline__ void split2(float a, float b, uint32_t& hi, uint32_t& lo) {
    __nv_bfloat16 ha = __float2bfloat16(a), hb = __float2bfloat16(b);
    __nv_bfloat16 la = __float2bfloat16(a - __bfloat162float(ha));
    __nv_bfloat16 lb = __float2bfloat16(b - __bfloat162float(hb));
    __nv_bfloat162 H; H.x = ha; H.y = hb;
    __nv_bfloat162 L; L.x = la; L.y = lb;
    hi = *(uint32_t*)&H;
    lo = *(uint32_t*)&L;
}

__device__ __forceinline__ void pair_bar(int wp) {
    asm volatile("bar.sync %0, %1;" :: "r"(wp + 1), "r"(64) : "memory");
}

__global__ __launch_bounds__(512, 1)
void sg_bf16(const float* __restrict__ x,
             const float* __restrict__ w1, const float* __restrict__ b1,
             const float* __restrict__ w2, const float* __restrict__ b2,
             float* __restrict__ out)
{
    extern __shared__ uint32_t sw[];
    float* smf = (float*)sw;

    const int tid = threadIdx.x;
    const int bid = blockIdx.x;
    const int b = bid >> 9, rem = bid & 511, h = rem >> 6, p = rem & 63;

    // ---- Phase A: load + bf16 hi/lo split (X, W1, W2, X^T), biases ----
    if (tid < 64) { smf[O_B1 + tid] = b1[tid]; smf[O_B2 + tid] = b2[tid]; }

    const float* xbase = x + ((size_t)b * LSEQ + p) * DMODEL + h * HEAD;
    {
        __nv_bfloat16* xth = (__nv_bfloat16*)(sw + O_XTHI);
        __nv_bfloat16* xtl = (__nv_bfloat16*)(sw + O_XTLO);
        for (int idx = tid; idx < NV * 32; idx += 512) {
            int i = idx >> 5, d2 = idx & 31;
            float2 v = *(const float2*)(xbase + (size_t)i * (PP * DMODEL) + 2 * d2);
            uint32_t hi, lo;
            split2(v.x, v.y, hi, lo);
            sw[O_XHI + i * WS + d2] = hi;
            sw[O_XLO + i * WS + d2] = lo;
            __nv_bfloat162 H = *(__nv_bfloat162*)&hi;
            __nv_bfloat162 L = *(__nv_bfloat162*)&lo;
            xth[(2 * d2) * (2 * PWS) + i]     = H.x;
            xth[(2 * d2 + 1) * (2 * PWS) + i] = H.y;
            xtl[(2 * d2) * (2 * PWS) + i]     = L.x;
            xtl[(2 * d2 + 1) * (2 * PWS) + i] = L.y;
        }
    }
    for (int idx = tid; idx < 64 * 32; idx += 512) {
        int r = idx >> 5, c2 = idx & 31;
        float2 v1 = *(const float2*)(w1 + r * 64 + 2 * c2);
        float2 v2 = *(const float2*)(w2 + r * 64 + 2 * c2);
        uint32_t hi, lo;
        split2(v1.x, v1.y, hi, lo);
        sw[O_W1HI + r * WS + c2] = hi; sw[O_W1LO + r * WS + c2] = lo;
        split2(v2.x, v2.y, hi, lo);
        sw[O_W2HI + r * WS + c2] = hi; sw[O_W2LO + r * WS + c2] = lo;
    }
    __syncthreads();

    const int warp = tid >> 5, lane = tid & 31;
    const int lr = lane >> 2, lc = lane & 3;
    const int wp = warp >> 1, wh = warp & 1;
    const int m0 = wp * 16;
    const int d0b = 32 * wh;

    // ---- Phase B: Q = X W1^T + b1, K = X W2^T + b2 (3-term bf16) ----
    {
        float cq[4][4] = {}, ck[4][4] = {};
        #pragma unroll
        for (int ks = 0; ks < 4; ks++) {
            const int wsb = ks * 8;
            const int r0 = (m0 + lr) * WS + wsb + lc, r1 = (m0 + lr + 8) * WS + wsb + lc;
            uint32_t ahi[4] = { sw[O_XHI + r0], sw[O_XHI + r1], sw[O_XHI + r0 + 4], sw[O_XHI + r1 + 4] };
            uint32_t alo[4] = { sw[O_XLO + r0], sw[O_XLO + r1], sw[O_XLO + r0 + 4], sw[O_XLO + r1 + 4] };
            #pragma unroll
            for (int n = 0; n < 4; n++) {
                const int rb = (d0b + n * 8 + lr) * WS + wsb + lc;
                uint32_t bh[2] = { sw[O_W1HI + rb], sw[O_W1HI + rb + 4] };
                uint32_t bl[2] = { sw[O_W1LO + rb], sw[O_W1LO + rb + 4] };
                mma16(cq[n], ahi, bh); mma16(cq[n], ahi, bl); mma16(cq[n], alo, bh);
                bh[0] = sw[O_W2HI + rb]; bh[1] = sw[O_W2HI + rb + 4];
                bl[0] = sw[O_W2LO + rb]; bl[1] = sw[O_W2LO + rb + 4];
                mma16(ck[n], ahi, bh); mma16(ck[n], ahi, bl); mma16(ck[n], alo, bh);
            }
        }
        // epilogue: +bias, split to Q/K hi/lo smem
        #pragma unroll
        for (int n = 0; n < 4; n++) {
            const int d0 = d0b + n * 8 + 2 * lc;
            const float bq0 = smf[O_B1 + d0], bq1 = smf[O_B1 + d0 + 1];
            const float bk0 = smf[O_B2 + d0], bk1 = smf[O_B2 + d0 + 1];
            const int cw = 16 * wh + 4 * n + lc;
            const int w0 = (m0 + lr) * WS + cw, w1i = (m0 + lr + 8) * WS + cw;
            uint32_t hi, lo;
            split2(cq[n][0] + bq0, cq[n][1] + bq1, hi, lo);
            sw[O_QHI + w0] = hi; sw[O_QLO + w0] = lo;
            split2(cq[n][2] + bq0, cq[n][3] + bq1, hi, lo);
            sw[O_QHI + w1i] = hi; sw[O_QLO + w1i] = lo;
            split2(ck[n][0] + bk0, ck[n][1] + bk1, hi, lo);
            sw[O_KHI + w0] = hi; sw[O_KLO + w0] = lo;
            split2(ck[n][2] + bk0, ck[n][3] + bk1, hi, lo);
            sw[O_KHI + w1i] = hi; sw[O_KLO + w1i] = lo;
        }
    }
    __syncthreads();

    // ---- Phase C: S = Q K^T (3-term bf16), gelu, register softmax, P -> smem ----
    float cs[8][4] = {};
    {
        const int c0 = 64 * wh;
        #pragma unroll
        for (int ks = 0; ks < 4; ks++) {
            const int wsb = ks * 8;
            const int r0 = (m0 + lr) * WS + wsb + lc, r1 = (m0 + lr + 8) * WS + wsb + lc;
            uint32_t ahi[4] = { sw[O_QHI + r0], sw[O_QHI + r1], sw[O_QHI + r0 + 4], sw[O_QHI + r1 + 4] };
            uint32_t alo[4] = { sw[O_QLO + r0], sw[O_QLO + r1], sw[O_QLO + r0 + 4], sw[O_QLO + r1 + 4] };
            #pragma unroll
            for (int n = 0; n < 8; n++) {
                const int rb = (c0 + n * 8 + lr) * WS + wsb + lc;
                uint32_t bh[2] = { sw[O_KHI + rb], sw[O_KHI + rb + 4] };
                uint32_t bl[2] = { sw[O_KLO + rb], sw[O_KLO + rb + 4] };
                mma16(cs[n], ahi, bh); mma16(cs[n], ahi, bl); mma16(cs[n], alo, bh);
            }
        }
    }

    // gelu (exact)
    #pragma unroll
    for (int n = 0; n < 8; n++)
        #pragma unroll
        for (int qq = 0; qq < 4; qq++) {
            float s = cs[n][qq];
            cs[n][qq] = 0.5f * s * (1.0f + erff(s * 0.70710678118654752f));
        }

    {
        float* redm = smf + O_RM;
        float* reds = smf + O_RS;
        float mA = -1e30f, mB = -1e30f;
        #pragma unroll
        for (int n = 0; n < 8; n++) {
            mA = fmaxf(mA, fmaxf(cs[n][0], cs[n][1]));
            mB = fmaxf(mB, fmaxf(cs[n][2], cs[n][3]));
        }
        mA = fmaxf(mA, __shfl_xor_sync(0xFFFFFFFF, mA, 1));
        mA = fmaxf(mA, __shfl_xor_sync(0xFFFFFFFF, mA, 2));
        mB = fmaxf(mB, __shfl_xor_sync(0xFFFFFFFF, mB, 1));
        mB = fmaxf(mB, __shfl_xor_sync(0xFFFFFFFF, mB, 2));
        if (lc == 0) {
            redm[wh * 128 + m0 + lr]     = mA;
            redm[wh * 128 + m0 + lr + 8] = mB;
        }
        pair_bar(wp);
        mA = fmaxf(redm[m0 + lr],     redm[128 + m0 + lr]);
        mB = fmaxf(redm[m0 + lr + 8], redm[128 + m0 + lr + 8]);

        float sA = 0.f, sB = 0.f;
        #pragma unroll
        for (int n = 0; n < 8; n++) {
            cs[n][0] = __expf(cs[n][0] - mA); sA += cs[n][0];
            cs[n][1] = __expf(cs[n][1] - mA); sA += cs[n][1];
            cs[n][2] = __expf(cs[n][2] - mB); sB += cs[n][2];
            cs[n][3] = __expf(cs[n][3] - mB); sB += cs[n][3];
        }
        sA += __shfl_xor_sync(0xFFFFFFFF, sA, 1);
        sA += __shfl_xor_sync(0xFFFFFFFF, sA, 2);
        sB += __shfl_xor_sync(0xFFFFFFFF, sB, 1);
        sB += __shfl_xor_sync(0xFFFFFFFF, sB, 2);
        if (lc == 0) {
            reds[wh * 128 + m0 + lr]     = sA;
            reds[wh * 128 + m0 + lr + 8] = sB;
        }
        pair_bar(wp);
        const float invA = 1.0f / (reds[m0 + lr]     + reds[128 + m0 + lr]);
        const float invB = 1.0f / (reds[m0 + lr + 8] + reds[128 + m0 + lr + 8]);

        // normalized P, bf16 hi/lo split, overlaid on dead X/W regions
        #pragma unroll
        for (int n = 0; n < 8; n++) {
            const int cw = 32 * wh + 4 * n + lc;
            uint32_t hi, lo;
            split2(cs[n][0] * invA, cs[n][1] * invA, hi, lo);
            const int w0 = (m0 + lr) * PWS + cw;
            sw[O_PHI + w0] = hi; sw[O_PLO + w0] = lo;
            split2(cs[n][2] * invB, cs[n][3] * invB, hi, lo);
            const int w1i = (m0 + lr + 8) * PWS + cw;
            sw[O_PHI + w1i] = hi; sw[O_PLO + w1i] = lo;
        }
        pair_bar(wp);
    }

    // ---- Phase D: Y = P X (3-term bf16 via X^T tiles) ----
    {
        float cy[4][4] = {};
        #pragma unroll
        for (int ks = 0; ks < 8; ks++) {
            const int wsb = ks * 8;
            const int r0 = (m0 + lr) * PWS + wsb + lc, r1 = (m0 + lr + 8) * PWS + wsb + lc;
            uint32_t ahi[4] = { sw[O_PHI + r0], sw[O_PHI + r1], sw[O_PHI + r0 + 4], sw[O_PHI + r1 + 4] };
            uint32_t alo[4] = { sw[O_PLO + r0], sw[O_PLO + r1], sw[O_PLO + r0 + 4], sw[O_PLO + r1 + 4] };
            #pragma unroll
            for (int n = 0; n < 4; n++) {
                const int rb = (d0b + n * 8 + lr) * PWS + wsb + lc;
                uint32_t bh[2] = { sw[O_XTHI + rb], sw[O_XTHI + rb + 4] };
                uint32_t bl[2] = { sw[O_XTLO + rb], sw[O_XTLO + rb + 4] };
                mma16(cy[n], ahi, bh); mma16(cy[n], ahi, bl); mma16(cy[n], alo, bh);
            }
        }

        const size_t ob0 = ((size_t)b * LSEQ + (size_t)(m0 + lr) * PP + p) * DMODEL + h * HEAD;
        const size_t ob1 = ((size_t)b * LSEQ + (size_t)(m0 + lr + 8) * PP + p) * DMODEL + h * HEAD;
        #pragma unroll
        for (int n = 0; n < 4; n++) {
            const int d0 = d0b + n * 8 + 2 * lc;
            *(float2*)(out + ob0 + d0) = make_float2(cy[n][0], cy[n][1]);
            *(float2*)(out + ob1 + d0) = make_float2(cy[n][2], cy[n][3]);
        }
    }
}

extern "C" void kernel_launch(void* const* d_in, const int* in_sizes, int n_in,
                              void* d_out, int out_size)
{
    const float* x  = (const float*)d_in[0];
    const float* w1 = (const float*)d_in[1];
    const float* b1 = (const float*)d_in[2];
    const float* w2 = (const float*)d_in[3];
    const float* b2 = (const float*)d_in[4];
    float* out = (float*)d_out;

    cudaFuncSetAttribute(sg_bf16, cudaFuncAttributeMaxDynamicSharedMemorySize, SMEM_BYTES);
    sg_bf16<<<BATCH * NHEADS * PP, 512, SMEM_BYTES>>>(x, w1, b1, w2, b2, out);
}